// round 6
// baseline (speedup 1.0000x reference)
#include <cuda_runtime.h>

typedef unsigned long long ull;

#define B   8
#define N   2048
#define E   256
#define M   1024
#define CD  32
#define O   512
#define NP  8192          // B*M
#define NPK 16384         // B*M*2
#define OUT_COOR_OFF 4194304   // B*O*M

// ---------------- scratch (static __device__ globals) ---------------------------
__device__ float g_D2[(size_t)B * N * N];        // 134 MB pairwise sq dists (keep in L2!)
__device__ float g_feaT[(size_t)B * N * E];      // 16 MB  fea transposed [b][n][e]
__device__ float g_ZT[(size_t)B * N * 1024];     // 64 MB  [bn][ Z1(512) | Z2(512) ]
__device__ float g_Y[(size_t)NPK * O];           // 32 MB  y [pk][o]
__device__ int   g_fps[B * M];
__device__ float g_scale[O];
__device__ float g_shift[O];

// ---------------- helpers --------------------------------------------------------
__device__ __forceinline__ ull pk2(float x) {
    unsigned u = __float_as_uint(x);
    ull r;
    asm("mov.b64 %0, {%1, %1};" : "=l"(r) : "r"(u));
    return r;
}
__device__ __forceinline__ void fma2(ull& d, ull a, ull b) {
    asm("fma.rn.f32x2 %0, %1, %2, %3;" : "=l"(d) : "l"(a), "l"(b), "l"(d));
}
__device__ __forceinline__ ull sub2(ull a, ull b, ull negone) {
    ull d;
    asm("fma.rn.f32x2 %0, %1, %2, %3;" : "=l"(d) : "l"(b), "l"(negone), "l"(a));
    return d;
}
__device__ __forceinline__ void unpk2(ull v, float& lo, float& hi) {
    unsigned a, b;
    asm("mov.b64 {%0, %1}, %2;" : "=r"(a), "=r"(b) : "l"(v));
    lo = __uint_as_float(a); hi = __uint_as_float(b);
}
__device__ __forceinline__ void pfL2(const void* p) {
    asm volatile("prefetch.global.L2 [%0];" :: "l"(p));
}
__device__ __forceinline__ ull umax64(ull a, ull b) { return a > b ? a : b; }

// ---------------- 1. PREP: d2 tiles (blocks 0..2047) + transpose (2048..6143) ----
__global__ __launch_bounds__(256) void k_prep(const float* __restrict__ coor,
                                              const float* __restrict__ fea) {
    __shared__ __align__(16) float sm[2 * 32 * 132];
    int t = threadIdx.x;
    if (blockIdx.x < 2048) {
        int gb  = blockIdx.x;
        int bb  = gb >> 8;
        int rem = gb & 255;
        int it = (rem >> 4) * 128, jt = (rem & 15) * 128;
        float (*sA)[132] = (float(*)[132])sm;
        float (*sB)[132] = (float(*)[132])(sm + 32 * 132);
        const float* cb = coor + (size_t)bb * N * CD;
#pragma unroll
        for (int q = 0; q < 4; q++) {
            int f = q * 256 + t;
            int row = f >> 3;
            int c4  = (f & 7) * 4;
            float4 va = *(const float4*)(cb + (size_t)(it + row) * CD + c4);
            sA[c4][row] = va.x; sA[c4 + 1][row] = va.y; sA[c4 + 2][row] = va.z; sA[c4 + 3][row] = va.w;
            float4 vb = *(const float4*)(cb + (size_t)(jt + row) * CD + c4);
            sB[c4][row] = vb.x; sB[c4 + 1][row] = vb.y; sB[c4 + 2][row] = vb.z; sB[c4 + 3][row] = vb.w;
        }
        __syncthreads();
        int tx = t & 15, ty = t >> 4;
        ull acc[8][4];
#pragma unroll
        for (int u = 0; u < 8; u++)
#pragma unroll
            for (int v = 0; v < 4; v++) acc[u][v] = 0ull;
        ull neg1 = pk2(-1.0f);
#pragma unroll
        for (int c = 0; c < CD; c++) {
            float4 fa = *(const float4*)&sA[c][ty * 8];
            float4 fb = *(const float4*)&sA[c][ty * 8 + 4];
            ull a2[8] = {pk2(fa.x), pk2(fa.y), pk2(fa.z), pk2(fa.w),
                         pk2(fb.x), pk2(fb.y), pk2(fb.z), pk2(fb.w)};
            const ull* pb = (const ull*)&sB[c][tx * 8];
            ull b2[4] = {pb[0], pb[1], pb[2], pb[3]};
#pragma unroll
            for (int u = 0; u < 8; u++)
#pragma unroll
                for (int v = 0; v < 4; v++) {
                    ull d = sub2(a2[u], b2[v], neg1);
                    fma2(acc[u][v], d, d);
                }
        }
        float* Drow = g_D2 + (size_t)bb * N * N;
#pragma unroll
        for (int u = 0; u < 8; u++) {
            float x0, x1, x2, x3, x4, x5, x6, x7;
            unpk2(acc[u][0], x0, x1); unpk2(acc[u][1], x2, x3);
            unpk2(acc[u][2], x4, x5); unpk2(acc[u][3], x6, x7);
            float* wp = Drow + (size_t)(it + ty * 8 + u) * N + jt + tx * 8;
            *(float4*)wp       = make_float4(x0, x1, x2, x3);   // allocate in L2
            *(float4*)(wp + 4) = make_float4(x4, x5, x6, x7);
        }
    } else {
        int tb  = blockIdx.x - 2048;
        int bb  = tb >> 9;
        int rem = tb & 511;
        int by = (rem >> 6) * 32, bx = (rem & 63) * 32;
        int tx = t & 31, ty = t >> 5;
        float (*tile)[33] = (float(*)[33])sm;
        const float* src = fea + (size_t)bb * E * N;
#pragma unroll
        for (int k = 0; k < 32; k += 8)
            tile[ty + k][tx] = src[(size_t)(by + ty + k) * N + bx + tx];
        __syncthreads();
        float* dst = g_feaT + (size_t)bb * N * E;
#pragma unroll
        for (int k = 0; k < 32; k += 8)   // evict-first: don't displace D2
            __stcs(&dst[(size_t)(bx + ty + k) * E + by + tx], tile[tx][ty + k]);
    }
}

// ---------------- 2. FUSED: fps (blocks 0..7) + Z-GEMM (blocks 8..1031) ----------
__global__ __launch_bounds__(256) void k_fused(const float* __restrict__ Wm) {
    __shared__ __align__(16) float smemF[2 * 16 * 132];
    __shared__ __align__(16) ull sred[2][8];
    int t = threadIdx.x;

    if (blockIdx.x < 8) {
        // ============================ FPS ========================================
        int bb   = blockIdx.x;
        int lane = t & 31, wid = t >> 5;
        const float* Db = g_D2 + (size_t)bb * N * N;
        float d0 = 1e10f, d1 = 1e10f, d2 = 1e10f, d3 = 1e10f;
        float d4 = 1e10f, d5 = 1e10f, d6 = 1e10f, d7 = 1e10f;
        int base = t * 8;
        int last = 0;
        if (t == 0) g_fps[bb * M] = 0;
        pfL2(Db + lane * 64);              // warm row 0 only
        pfL2(Db + lane * 64 + 32);
        for (int s = 1; s < M; s++) {
            const float4* rp = (const float4*)(Db + (size_t)last * N);
            float4 ra = rp[2 * t], rb = rp[2 * t + 1];
            d0 = fminf(d0, ra.x); d1 = fminf(d1, ra.y);
            d2 = fminf(d2, ra.z); d3 = fminf(d3, ra.w);
            d4 = fminf(d4, rb.x); d5 = fminf(d5, rb.y);
            d6 = fminf(d6, rb.z); d7 = fminf(d7, rb.w);
            float vA = (d1 > d0) ? d1 : d0;  int jA = (d1 > d0) ? base + 1 : base;
            float vB = (d3 > d2) ? d3 : d2;  int jB = (d3 > d2) ? base + 3 : base + 2;
            float vC = (d5 > d4) ? d5 : d4;  int jC = (d5 > d4) ? base + 5 : base + 4;
            float vD = (d7 > d6) ? d7 : d6;  int jD = (d7 > d6) ? base + 7 : base + 6;
            float vAB = (vB > vA) ? vB : vA; int jAB = (vB > vA) ? jB : jA;
            float vCD = (vD > vC) ? vD : vC; int jCD = (vD > vC) ? jD : jC;
            float v   = (vCD > vAB) ? vCD : vAB;
            int   j   = (vCD > vAB) ? jCD : jAB;
            unsigned key  = __float_as_uint(v);
            unsigned wmax = __reduce_max_sync(0xffffffffu, key);
            unsigned ball = __ballot_sync(0xffffffffu, key == wmax);
            int src  = __ffs(ball) - 1;                 // lowest lane = lowest col
            int widx = __shfl_sync(0xffffffffu, j, src);
            if (lane == 0)   // ~widx: u64-max then picks LOWEST index on value tie
                sred[s & 1][wid] = ((ull)wmax << 32) | (unsigned)(~(unsigned)widx);
            __syncthreads();
            // stage-2: every thread reads all 8 entries (broadcast LDS) + local tree
            const ull* sp = sred[s & 1];
            ull m = umax64(umax64(umax64(sp[0], sp[1]), umax64(sp[2], sp[3])),
                           umax64(umax64(sp[4], sp[5]), umax64(sp[6], sp[7])));
            last = (int)(~(unsigned)(m & 0xffffffffu));
            if (t == 0) g_fps[bb * M + s] = last;
        }
    } else {
        // ================ Z-GEMM (evict-first traffic; protect D2 in L2) =========
        int gb = blockIdx.x - 8;
        int ot = gb & 7, nt = gb >> 3;
        int ob = ot * 128, nb = nt * 128;
        float (*sF)[132] = (float(*)[132])smemF;
        float (*sG)[132] = (float(*)[132])(smemF + 16 * 132);
        int tx = t & 15, ty = t >> 4;
        ull acc[8][4];
#pragma unroll
        for (int u = 0; u < 8; u++)
#pragma unroll
            for (int v = 0; v < 4; v++) acc[u][v] = 0ull;

        for (int c0 = 0; c0 < 256; c0 += 16) {
#pragma unroll
            for (int q = 0; q < 2; q++) {
                int f  = q * 256 + t;
                int r  = f >> 2;
                int c4 = (f & 3) * 4;
                float4 va = __ldcs((const float4*)(g_feaT + (size_t)(nb + r) * E + c0 + c4));
                sF[c4][r] = va.x; sF[c4 + 1][r] = va.y; sF[c4 + 2][r] = va.z; sF[c4 + 3][r] = va.w;
                float4 wv;
                if (ob < 512) {
                    wv = *(const float4*)(Wm + (size_t)(ob + r) * 512 + c0 + c4);
                } else {
                    const float* wr = Wm + (size_t)(ob + r - 512) * 512;
                    float4 w1 = *(const float4*)(wr + c0 + c4);
                    float4 w2 = *(const float4*)(wr + 256 + c0 + c4);
                    wv = make_float4(w2.x - w1.x, w2.y - w1.y, w2.z - w1.z, w2.w - w1.w);
                }
                sG[c4][r] = wv.x; sG[c4 + 1][r] = wv.y; sG[c4 + 2][r] = wv.z; sG[c4 + 3][r] = wv.w;
            }
            __syncthreads();
#pragma unroll
            for (int k = 0; k < 16; k++) {
                float4 fa = *(const float4*)&sF[k][ty * 8];
                float4 fb = *(const float4*)&sF[k][ty * 8 + 4];
                ull a2[8] = {pk2(fa.x), pk2(fa.y), pk2(fa.z), pk2(fa.w),
                             pk2(fb.x), pk2(fb.y), pk2(fb.z), pk2(fb.w)};
                const ull* pb = (const ull*)&sG[k][tx * 8];
                ull b0 = pb[0], b1 = pb[1], b2v = pb[2], b3 = pb[3];
#pragma unroll
                for (int u = 0; u < 8; u++) {
                    fma2(acc[u][0], a2[u], b0);
                    fma2(acc[u][1], a2[u], b1);
                    fma2(acc[u][2], a2[u], b2v);
                    fma2(acc[u][3], a2[u], b3);
                }
            }
            __syncthreads();
        }
#pragma unroll
        for (int u = 0; u < 8; u++) {
            float x0, x1, x2, x3, x4, x5, x6, x7;
            unpk2(acc[u][0], x0, x1); unpk2(acc[u][1], x2, x3);
            unpk2(acc[u][2], x4, x5); unpk2(acc[u][3], x6, x7);
            float* zr = g_ZT + (size_t)(nb + ty * 8 + u) * 1024 + ob + tx * 8;
            __stcs((float4*)zr,       make_float4(x0, x1, x2, x3));
            __stcs((float4*)(zr + 4), make_float4(x4, x5, x6, x7));
        }
    }
}

// ---------------- 3. knn top-2 + assemble y (blocks 0..1023) + coor (1024..2047) -
__global__ __launch_bounds__(256) void k_knn(const float* __restrict__ coor,
                                             float* __restrict__ out2) {
    if (blockIdx.x < 1024) {
        int gw   = (blockIdx.x * 256 + threadIdx.x) >> 5;   // point id p = bb*M+j
        int lane = threadIdx.x & 31;
        int bb = gw >> 10, j = gw & 1023;
        int r  = g_fps[bb * M + j];
        const float4* row = (const float4*)(g_D2 + (size_t)bb * N * N + (size_t)r * N);
        ull p1 = ~0ull, p2 = ~0ull;
        for (int c4 = lane; c4 < N / 4; c4 += 32) {
            float4 v = __ldcs(row + c4);
            unsigned col = 4 * c4;
            ull k0 = ((ull)__float_as_uint(v.x) << 32) | col;
            ull k1 = ((ull)__float_as_uint(v.y) << 32) | (col + 1);
            ull k2 = ((ull)__float_as_uint(v.z) << 32) | (col + 2);
            ull k3 = ((ull)__float_as_uint(v.w) << 32) | (col + 3);
            if (k0 < p1) { p2 = p1; p1 = k0; } else if (k0 < p2) p2 = k0;
            if (k1 < p1) { p2 = p1; p1 = k1; } else if (k1 < p2) p2 = k1;
            if (k2 < p1) { p2 = p1; p1 = k2; } else if (k2 < p2) p2 = k2;
            if (k3 < p1) { p2 = p1; p1 = k3; } else if (k3 < p2) p2 = k3;
        }
#pragma unroll
        for (int off = 16; off; off >>= 1) {
            ull q1 = __shfl_down_sync(0xffffffffu, p1, off);
            ull q2 = __shfl_down_sync(0xffffffffu, p2, off);
            ull n1 = p1 < q1 ? p1 : q1;
            ull m1 = p1 < q1 ? q1 : p1;
            ull n2 = p2 < q2 ? p2 : q2;
            p1 = n1;
            p2 = m1 < n2 ? m1 : n2;
        }
        int n1 = __shfl_sync(0xffffffffu, (int)(p1 & 0xffffffffu), 0);
        int n2 = __shfl_sync(0xffffffffu, (int)(p2 & 0xffffffffu), 0);
        // ---- assemble y[2p][:] and y[2p+1][:] directly (fused old k_asm) ----
        const float* z1a = g_ZT + (size_t)(bb * N + n1) * 1024;
        const float* z1b = g_ZT + (size_t)(bb * N + n2) * 1024;
        const float* z2  = g_ZT + (size_t)(bb * N + r)  * 1024 + 512;
        float* y0 = g_Y + (size_t)(2 * gw) * O;
        float* y1 = y0 + O;
#pragma unroll
        for (int q = 0; q < 4; q++) {
            int o4 = (lane + 32 * q) * 4;
            float4 c = __ldcs((const float4*)(z2 + o4));
            float4 a = __ldcs((const float4*)(z1a + o4));
            float4 b = __ldcs((const float4*)(z1b + o4));
            *(float4*)(y0 + o4) = make_float4(a.x + c.x, a.y + c.y, a.z + c.z, a.w + c.w);
            *(float4*)(y1 + o4) = make_float4(b.x + c.x, b.y + c.y, b.z + c.z, b.w + c.w);
        }
    } else {
        int lin = (blockIdx.x - 1024) * 256 + threadIdx.x;  // B*M*CD
        int cc = lin & 31;
        int j  = (lin >> 5) & 1023;
        int bb = lin >> 15;
        int r  = g_fps[bb * M + j];
        out2[lin] = coor[(size_t)bb * N * CD + (size_t)r * CD + cc];
    }
}

// ---------------- 4. BN stats (deterministic) ------------------------------------
__global__ __launch_bounds__(256) void k_stats(const float* __restrict__ gamma,
                                               const float* __restrict__ beta) {
    int t   = threadIdx.x;
    int ocb = blockIdx.x * 32;
    int o   = ocb + (t & 31);
    int h   = t >> 5;
    float s = 0.f, s2 = 0.f;
    for (int r = h; r < NPK; r += 8) {
        float v = g_Y[(size_t)r * O + o];
        s += v;
        s2 = fmaf(v, v, s2);
    }
    __shared__ float ps[8][32], ps2[8][32];
    ps[h][t & 31] = s; ps2[h][t & 31] = s2;
    __syncthreads();
    if (t < 32) {
        float ss = 0.f, ss2 = 0.f;
#pragma unroll
        for (int i = 0; i < 8; i++) { ss += ps[i][t]; ss2 += ps2[i][t]; }
        float mu   = ss / (float)NPK;
        float var  = ss2 / (float)NPK - mu * mu;
        float rstd = rsqrtf(var + 1e-5f);
        float sc   = gamma[ocb + t] * rstd;
        g_scale[ocb + t] = sc;
        g_shift[ocb + t] = beta[ocb + t] - mu * sc;
    }
}

// ---------------- 5. BN apply + relu + max_k + transpose -> out[b][o][m] ---------
__global__ __launch_bounds__(256) void k_final(float* __restrict__ out) {
    __shared__ float sm[128][33];
    int t   = threadIdx.x;
    int jt  = blockIdx.x * 64;
    int ocb = blockIdx.y * 32;
    int bb  = blockIdx.z;
    size_t pk0 = ((size_t)bb * M + jt) * 2;
#pragma unroll
    for (int q = 0; q < 4; q++) {
        int f = q * 256 + t;
        int row = f >> 3;
        int oq  = (f & 7) * 4;
        float4 v = *(const float4*)(g_Y + (pk0 + row) * O + ocb + oq);
        sm[row][oq] = v.x; sm[row][oq + 1] = v.y; sm[row][oq + 2] = v.z; sm[row][oq + 3] = v.w;
    }
    __syncthreads();
    int oo = t >> 3;
    int jb = (t & 7) * 8;
    float sc = g_scale[ocb + oo], sh = g_shift[ocb + oo];
    float res[8];
#pragma unroll
    for (int jj = 0; jj < 8; jj++) {
        int r = 2 * (jb + jj);
        float a = fmaf(sm[r][oo],     sc, sh);
        float b = fmaf(sm[r + 1][oo], sc, sh);
        res[jj] = fmaxf(fmaxf(a, b), 0.f);
    }
    float* op = out + ((size_t)bb * O + ocb + oo) * M + jt + jb;
    *(float4*)op       = make_float4(res[0], res[1], res[2], res[3]);
    *(float4*)(op + 4) = make_float4(res[4], res[5], res[6], res[7]);
}

// ---------------- launch ---------------------------------------------------------
extern "C" void kernel_launch(void* const* d_in, const int* in_sizes, int n_in,
                              void* d_out, int out_size) {
    const float* fea   = (const float*)d_in[0];
    const float* coor  = (const float*)d_in[1];
    const float* Wm    = (const float*)d_in[2];
    const float* gamma = (const float*)d_in[4];
    const float* beta  = (const float*)d_in[5];
    float* out  = (float*)d_out;
    float* out2 = out + OUT_COOR_OFF;

    k_prep<<<2048 + 4096, 256>>>(coor, fea);      // d2 + transpose, one wave
    k_fused<<<8 + 1024, 256>>>(Wm);               // fps blocks 0..7; GEMM hidden under it
    k_knn<<<2048, 256>>>(coor, out2);             // knn + y-assembly + coor gather
    k_stats<<<O / 32, 256>>>(gamma, beta);
    k_final<<<dim3(M / 64, O / 32, B), 256>>>(out);
}

// round 7
// speedup vs baseline: 1.3560x; 1.3560x over previous
#include <cuda_runtime.h>

typedef unsigned long long ull;

#define B   8
#define N   2048
#define E   256
#define M   1024
#define CD  32
#define O   512
#define NP  8192          // B*M
#define NPK 16384         // B*M*2
#define OUT_COOR_OFF 4194304   // B*O*M
#define SPART 128         // stats partial blocks

// ---------------- scratch (static __device__ globals) ---------------------------
__device__ float g_D2[(size_t)B * N * N];        // 134 MB pairwise sq dists (keep in L2!)
__device__ float g_feaT[(size_t)B * N * E];      // 16 MB  fea transposed [b][n][e]
__device__ float g_ZT[(size_t)B * N * 1024];     // 64 MB  [bn][ Z1(512) | Z2(512) ]
__device__ float g_Y[(size_t)NPK * O];           // 32 MB  y [pk][o]
__device__ int   g_fps[B * M];
__device__ float g_partS[SPART * O];
__device__ float g_partQ[SPART * O];
__device__ float g_scale[O];
__device__ float g_shift[O];

// ---------------- helpers --------------------------------------------------------
__device__ __forceinline__ ull pk2(float x) {
    unsigned u = __float_as_uint(x);
    ull r;
    asm("mov.b64 %0, {%1, %1};" : "=l"(r) : "r"(u));
    return r;
}
__device__ __forceinline__ void fma2(ull& d, ull a, ull b) {
    asm("fma.rn.f32x2 %0, %1, %2, %3;" : "=l"(d) : "l"(a), "l"(b), "l"(d));
}
__device__ __forceinline__ ull sub2(ull a, ull b, ull negone) {
    ull d;
    asm("fma.rn.f32x2 %0, %1, %2, %3;" : "=l"(d) : "l"(b), "l"(negone), "l"(a));
    return d;
}
__device__ __forceinline__ void unpk2(ull v, float& lo, float& hi) {
    unsigned a, b;
    asm("mov.b64 {%0, %1}, %2;" : "=r"(a), "=r"(b) : "l"(v));
    lo = __uint_as_float(a); hi = __uint_as_float(b);
}
__device__ __forceinline__ void pfL2(const void* p) {
    asm volatile("prefetch.global.L2 [%0];" :: "l"(p));
}

// ---------------- 1. PREP: d2 tiles (blocks 0..2047) + transpose (2048..6143) ----
__global__ __launch_bounds__(256) void k_prep(const float* __restrict__ coor,
                                              const float* __restrict__ fea) {
    __shared__ __align__(16) float sm[2 * 32 * 132];
    int t = threadIdx.x;
    if (blockIdx.x < 2048) {
        int gb  = blockIdx.x;
        int bb  = gb >> 8;
        int rem = gb & 255;
        int it = (rem >> 4) * 128, jt = (rem & 15) * 128;
        float (*sA)[132] = (float(*)[132])sm;
        float (*sB)[132] = (float(*)[132])(sm + 32 * 132);
        const float* cb = coor + (size_t)bb * N * CD;
#pragma unroll
        for (int q = 0; q < 4; q++) {
            int f = q * 256 + t;
            int row = f >> 3;
            int c4  = (f & 7) * 4;
            float4 va = *(const float4*)(cb + (size_t)(it + row) * CD + c4);
            sA[c4][row] = va.x; sA[c4 + 1][row] = va.y; sA[c4 + 2][row] = va.z; sA[c4 + 3][row] = va.w;
            float4 vb = *(const float4*)(cb + (size_t)(jt + row) * CD + c4);
            sB[c4][row] = vb.x; sB[c4 + 1][row] = vb.y; sB[c4 + 2][row] = vb.z; sB[c4 + 3][row] = vb.w;
        }
        __syncthreads();
        int tx = t & 15, ty = t >> 4;
        ull acc[8][4];
#pragma unroll
        for (int u = 0; u < 8; u++)
#pragma unroll
            for (int v = 0; v < 4; v++) acc[u][v] = 0ull;
        ull neg1 = pk2(-1.0f);
#pragma unroll
        for (int c = 0; c < CD; c++) {
            float4 fa = *(const float4*)&sA[c][ty * 8];
            float4 fb = *(const float4*)&sA[c][ty * 8 + 4];
            ull a2[8] = {pk2(fa.x), pk2(fa.y), pk2(fa.z), pk2(fa.w),
                         pk2(fb.x), pk2(fb.y), pk2(fb.z), pk2(fb.w)};
            const ull* pb = (const ull*)&sB[c][tx * 8];
            ull b2[4] = {pb[0], pb[1], pb[2], pb[3]};
#pragma unroll
            for (int u = 0; u < 8; u++)
#pragma unroll
                for (int v = 0; v < 4; v++) {
                    ull d = sub2(a2[u], b2[v], neg1);
                    fma2(acc[u][v], d, d);
                }
        }
        float* Drow = g_D2 + (size_t)bb * N * N;
#pragma unroll
        for (int u = 0; u < 8; u++) {
            float x0, x1, x2, x3, x4, x5, x6, x7;
            unpk2(acc[u][0], x0, x1); unpk2(acc[u][1], x2, x3);
            unpk2(acc[u][2], x4, x5); unpk2(acc[u][3], x6, x7);
            float* wp = Drow + (size_t)(it + ty * 8 + u) * N + jt + tx * 8;
            *(float4*)wp       = make_float4(x0, x1, x2, x3);   // allocate in L2
            *(float4*)(wp + 4) = make_float4(x4, x5, x6, x7);
        }
    } else {
        int tb  = blockIdx.x - 2048;
        int bb  = tb >> 9;
        int rem = tb & 511;
        int by = (rem >> 6) * 32, bx = (rem & 63) * 32;
        int tx = t & 31, ty = t >> 5;
        float (*tile)[33] = (float(*)[33])sm;
        const float* src = fea + (size_t)bb * E * N;
#pragma unroll
        for (int k = 0; k < 32; k += 8)
            tile[ty + k][tx] = src[(size_t)(by + ty + k) * N + bx + tx];
        __syncthreads();
        float* dst = g_feaT + (size_t)bb * N * E;
#pragma unroll
        for (int k = 0; k < 32; k += 8)   // evict-first: don't displace D2
            __stcs(&dst[(size_t)(bx + ty + k) * E + by + tx], tile[tx][ty + k]);
    }
}

// ---------------- 2. FUSED: fps (blocks 0..7) + Z-GEMM (blocks 8..1031) ----------
__global__ __launch_bounds__(256) void k_fused(const float* __restrict__ Wm) {
    __shared__ __align__(16) float smemF[2 * 16 * 132];
    __shared__ ull sred[2][8];
    int t = threadIdx.x;

    if (blockIdx.x < 8) {
        // ============== FPS (R3-exact: L2 candidate prefetch + REDUX stage2) =====
        int bb   = blockIdx.x;
        int lane = t & 31, wid = t >> 5;
        const float* Db = g_D2 + (size_t)bb * N * N;
        float d0 = 1e10f, d1 = 1e10f, d2 = 1e10f, d3 = 1e10f;
        float d4 = 1e10f, d5 = 1e10f, d6 = 1e10f, d7 = 1e10f;
        int base = t * 8;
        int last = 0;
        if (t == 0) g_fps[bb * M] = 0;
        pfL2(Db + lane * 64);
        pfL2(Db + lane * 64 + 32);
        for (int s = 1; s < M; s++) {
            const float4* rp = (const float4*)(Db + (size_t)last * N);
            float4 ra = rp[2 * t], rb = rp[2 * t + 1];
            d0 = fminf(d0, ra.x); d1 = fminf(d1, ra.y);
            d2 = fminf(d2, ra.z); d3 = fminf(d3, ra.w);
            d4 = fminf(d4, rb.x); d5 = fminf(d5, rb.y);
            d6 = fminf(d6, rb.z); d7 = fminf(d7, rb.w);
            float vA = (d1 > d0) ? d1 : d0;  int jA = (d1 > d0) ? base + 1 : base;
            float vB = (d3 > d2) ? d3 : d2;  int jB = (d3 > d2) ? base + 3 : base + 2;
            float vC = (d5 > d4) ? d5 : d4;  int jC = (d5 > d4) ? base + 5 : base + 4;
            float vD = (d7 > d6) ? d7 : d6;  int jD = (d7 > d6) ? base + 7 : base + 6;
            float vAB = (vB > vA) ? vB : vA; int jAB = (vB > vA) ? jB : jA;
            float vCD = (vD > vC) ? vD : vC; int jCD = (vD > vC) ? jD : jC;
            float v   = (vCD > vAB) ? vCD : vAB;
            int   j   = (vCD > vAB) ? jCD : jAB;
            unsigned key  = __float_as_uint(v);
            unsigned wmax = __reduce_max_sync(0xffffffffu, key);
            unsigned ball = __ballot_sync(0xffffffffu, key == wmax);
            int src  = __ffs(ball) - 1;
            int widx = __shfl_sync(0xffffffffu, j, src);   // warp candidate
            // speculative: pull this warp's candidate row toward L2/L1 (no sync cost)
            {
                const float* prow = Db + (size_t)widx * N + lane * 64;
                pfL2(prow);
                pfL2(prow + 32);
            }
            if (lane == 0)
                sred[s & 1][wid] = ((ull)wmax << 32) | (unsigned)widx;
            __syncthreads();
            // stage-2, redundant in all warps (prefetches in flight meanwhile)
            ull kv = sred[s & 1][lane & 7];
            unsigned hv   = (unsigned)(kv >> 32);
            unsigned hmax = __reduce_max_sync(0xffffffffu, hv);
            unsigned bl2  = __ballot_sync(0xffffffffu, hv == hmax);
            int src2 = __ffs(bl2) - 1;
            last = __shfl_sync(0xffffffffu, (int)(unsigned)(kv & 0xffffffffu), src2);
            if (t == 0) g_fps[bb * M + s] = last;
        }
    } else {
        // ================ Z-GEMM (evict-first traffic; protect D2 in L2) =========
        int gb = blockIdx.x - 8;
        int ot = gb & 7, nt = gb >> 3;
        int ob = ot * 128, nb = nt * 128;
        float (*sF)[132] = (float(*)[132])smemF;
        float (*sG)[132] = (float(*)[132])(smemF + 16 * 132);
        int tx = t & 15, ty = t >> 4;
        ull acc[8][4];
#pragma unroll
        for (int u = 0; u < 8; u++)
#pragma unroll
            for (int v = 0; v < 4; v++) acc[u][v] = 0ull;

        for (int c0 = 0; c0 < 256; c0 += 16) {
#pragma unroll
            for (int q = 0; q < 2; q++) {
                int f  = q * 256 + t;
                int r  = f >> 2;
                int c4 = (f & 3) * 4;
                float4 va = __ldcs((const float4*)(g_feaT + (size_t)(nb + r) * E + c0 + c4));
                sF[c4][r] = va.x; sF[c4 + 1][r] = va.y; sF[c4 + 2][r] = va.z; sF[c4 + 3][r] = va.w;
                float4 wv;
                if (ob < 512) {
                    wv = *(const float4*)(Wm + (size_t)(ob + r) * 512 + c0 + c4);
                } else {
                    const float* wr = Wm + (size_t)(ob + r - 512) * 512;
                    float4 w1 = *(const float4*)(wr + c0 + c4);
                    float4 w2 = *(const float4*)(wr + 256 + c0 + c4);
                    wv = make_float4(w2.x - w1.x, w2.y - w1.y, w2.z - w1.z, w2.w - w1.w);
                }
                sG[c4][r] = wv.x; sG[c4 + 1][r] = wv.y; sG[c4 + 2][r] = wv.z; sG[c4 + 3][r] = wv.w;
            }
            __syncthreads();
#pragma unroll
            for (int k = 0; k < 16; k++) {
                float4 fa = *(const float4*)&sF[k][ty * 8];
                float4 fb = *(const float4*)&sF[k][ty * 8 + 4];
                ull a2[8] = {pk2(fa.x), pk2(fa.y), pk2(fa.z), pk2(fa.w),
                             pk2(fb.x), pk2(fb.y), pk2(fb.z), pk2(fb.w)};
                const ull* pb = (const ull*)&sG[k][tx * 8];
                ull b0 = pb[0], b1 = pb[1], b2v = pb[2], b3 = pb[3];
#pragma unroll
                for (int u = 0; u < 8; u++) {
                    fma2(acc[u][0], a2[u], b0);
                    fma2(acc[u][1], a2[u], b1);
                    fma2(acc[u][2], a2[u], b2v);
                    fma2(acc[u][3], a2[u], b3);
                }
            }
            __syncthreads();
        }
#pragma unroll
        for (int u = 0; u < 8; u++) {
            float x0, x1, x2, x3, x4, x5, x6, x7;
            unpk2(acc[u][0], x0, x1); unpk2(acc[u][1], x2, x3);
            unpk2(acc[u][2], x4, x5); unpk2(acc[u][3], x6, x7);
            float* zr = g_ZT + (size_t)(nb + ty * 8 + u) * 1024 + ob + tx * 8;
            __stcs((float4*)zr,       make_float4(x0, x1, x2, x3));
            __stcs((float4*)(zr + 4), make_float4(x4, x5, x6, x7));
        }
    }
}

// ---------------- 3. knn top-2 + assemble y (blocks 0..1023) + coor (1024..2047) -
__global__ __launch_bounds__(256) void k_knn(const float* __restrict__ coor,
                                             float* __restrict__ out2) {
    if (blockIdx.x < 1024) {
        int gw   = (blockIdx.x * 256 + threadIdx.x) >> 5;   // point id p = bb*M+j
        int lane = threadIdx.x & 31;
        int bb = gw >> 10, j = gw & 1023;
        int r  = g_fps[bb * M + j];
        const float4* row = (const float4*)(g_D2 + (size_t)bb * N * N + (size_t)r * N);
        ull p1 = ~0ull, p2 = ~0ull;
        for (int c4 = lane; c4 < N / 4; c4 += 32) {
            float4 v = __ldcs(row + c4);
            unsigned col = 4 * c4;
            ull k0 = ((ull)__float_as_uint(v.x) << 32) | col;
            ull k1 = ((ull)__float_as_uint(v.y) << 32) | (col + 1);
            ull k2 = ((ull)__float_as_uint(v.z) << 32) | (col + 2);
            ull k3 = ((ull)__float_as_uint(v.w) << 32) | (col + 3);
            if (k0 < p1) { p2 = p1; p1 = k0; } else if (k0 < p2) p2 = k0;
            if (k1 < p1) { p2 = p1; p1 = k1; } else if (k1 < p2) p2 = k1;
            if (k2 < p1) { p2 = p1; p1 = k2; } else if (k2 < p2) p2 = k2;
            if (k3 < p1) { p2 = p1; p1 = k3; } else if (k3 < p2) p2 = k3;
        }
#pragma unroll
        for (int off = 16; off; off >>= 1) {
            ull q1 = __shfl_down_sync(0xffffffffu, p1, off);
            ull q2 = __shfl_down_sync(0xffffffffu, p2, off);
            ull n1 = p1 < q1 ? p1 : q1;
            ull m1 = p1 < q1 ? q1 : p1;
            ull n2 = p2 < q2 ? p2 : q2;
            p1 = n1;
            p2 = m1 < n2 ? m1 : n2;
        }
        int n1 = __shfl_sync(0xffffffffu, (int)(p1 & 0xffffffffu), 0);
        int n2 = __shfl_sync(0xffffffffu, (int)(p2 & 0xffffffffu), 0);
        // ---- assemble y[2p][:] and y[2p+1][:] directly ----
        const float* z1a = g_ZT + (size_t)(bb * N + n1) * 1024;
        const float* z1b = g_ZT + (size_t)(bb * N + n2) * 1024;
        const float* z2  = g_ZT + (size_t)(bb * N + r)  * 1024 + 512;
        float* y0 = g_Y + (size_t)(2 * gw) * O;
        float* y1 = y0 + O;
#pragma unroll
        for (int q = 0; q < 4; q++) {
            int o4 = (lane + 32 * q) * 4;
            float4 c = __ldcs((const float4*)(z2 + o4));
            float4 a = __ldcs((const float4*)(z1a + o4));
            float4 b = __ldcs((const float4*)(z1b + o4));
            *(float4*)(y0 + o4) = make_float4(a.x + c.x, a.y + c.y, a.z + c.z, a.w + c.w);
            *(float4*)(y1 + o4) = make_float4(b.x + c.x, b.y + c.y, b.z + c.z, b.w + c.w);
        }
    } else {
        int lin = (blockIdx.x - 1024) * 256 + threadIdx.x;  // B*M*CD
        int cc = lin & 31;
        int j  = (lin >> 5) & 1023;
        int bb = lin >> 15;
        int r  = g_fps[bb * M + j];
        out2[lin] = coor[(size_t)bb * N * CD + (size_t)r * CD + cc];
    }
}

// ---------------- 4a. BN stats phase A: 128 partial blocks -----------------------
__global__ __launch_bounds__(256) void k_stats_part() {
    int blk = blockIdx.x;                 // 0..127, rows blk*128 .. +127
    int t   = threadIdx.x;                // channel pair: 2t, 2t+1
    const float* yp = g_Y + (size_t)blk * 128 * O + 2 * t;
    float sx = 0.f, sy = 0.f, qx = 0.f, qy = 0.f;
#pragma unroll 8
    for (int r = 0; r < 128; r++) {
        float2 v = *(const float2*)(yp + (size_t)r * O);
        sx += v.x;  sy += v.y;
        qx = fmaf(v.x, v.x, qx);
        qy = fmaf(v.y, v.y, qy);
    }
    *(float2*)&g_partS[blk * O + 2 * t] = make_float2(sx, sy);
    *(float2*)&g_partQ[blk * O + 2 * t] = make_float2(qx, qy);
}

// ---------------- 4b. BN stats finisher: reduce 128 partials per channel ---------
__global__ __launch_bounds__(256) void k_stats_fin(const float* __restrict__ gamma,
                                                   const float* __restrict__ beta) {
    int o = blockIdx.x * 256 + threadIdx.x;    // 0..511
    float s = 0.f, q = 0.f;
#pragma unroll 8
    for (int i = 0; i < SPART; i++) {          // fixed order: deterministic
        s += g_partS[i * O + o];
        q += g_partQ[i * O + o];
    }
    float mu   = s / (float)NPK;
    float var  = q / (float)NPK - mu * mu;
    float rstd = rsqrtf(var + 1e-5f);
    float sc   = gamma[o] * rstd;
    g_scale[o] = sc;
    g_shift[o] = beta[o] - mu * sc;
}

// ---------------- 5. BN apply + relu + max_k + transpose -> out[b][o][m] ---------
__global__ __launch_bounds__(256) void k_final(float* __restrict__ out) {
    __shared__ float sm[128][33];
    int t   = threadIdx.x;
    int jt  = blockIdx.x * 64;
    int ocb = blockIdx.y * 32;
    int bb  = blockIdx.z;
    size_t pk0 = ((size_t)bb * M + jt) * 2;
#pragma unroll
    for (int q = 0; q < 4; q++) {
        int f = q * 256 + t;
        int row = f >> 3;
        int oq  = (f & 7) * 4;
        float4 v = *(const float4*)(g_Y + (pk0 + row) * O + ocb + oq);
        sm[row][oq] = v.x; sm[row][oq + 1] = v.y; sm[row][oq + 2] = v.z; sm[row][oq + 3] = v.w;
    }
    __syncthreads();
    int oo = t >> 3;
    int jb = (t & 7) * 8;
    float sc = g_scale[ocb + oo], sh = g_shift[ocb + oo];
    float res[8];
#pragma unroll
    for (int jj = 0; jj < 8; jj++) {
        int r = 2 * (jb + jj);
        float a = fmaf(sm[r][oo],     sc, sh);
        float b = fmaf(sm[r + 1][oo], sc, sh);
        res[jj] = fmaxf(fmaxf(a, b), 0.f);
    }
    float* op = out + ((size_t)bb * O + ocb + oo) * M + jt + jb;
    *(float4*)op       = make_float4(res[0], res[1], res[2], res[3]);
    *(float4*)(op + 4) = make_float4(res[4], res[5], res[6], res[7]);
}

// ---------------- launch ---------------------------------------------------------
extern "C" void kernel_launch(void* const* d_in, const int* in_sizes, int n_in,
                              void* d_out, int out_size) {
    const float* fea   = (const float*)d_in[0];
    const float* coor  = (const float*)d_in[1];
    const float* Wm    = (const float*)d_in[2];
    const float* gamma = (const float*)d_in[4];
    const float* beta  = (const float*)d_in[5];
    float* out  = (float*)d_out;
    float* out2 = out + OUT_COOR_OFF;

    k_prep<<<2048 + 4096, 256>>>(coor, fea);      // d2 + transpose, one wave
    k_fused<<<8 + 1024, 256>>>(Wm);               // fps blocks 0..7; GEMM hidden under it
    k_knn<<<2048, 256>>>(coor, out2);             // knn + y-assembly + coor gather
    k_stats_part<<<SPART, 256>>>();               // parallel BN partials
    k_stats_fin<<<2, 256>>>(gamma, beta);         // reduce + scale/shift
    k_final<<<dim3(M / 64, O / 32, B), 256>>>(out);
}